// round 6
// baseline (speedup 1.0000x reference)
#include <cuda_runtime.h>

#define NN 1024
#define NB 8

typedef unsigned long long u64;

// ---------------- scratch (static device globals: allowed) ----------------
static __device__ float  g_S[512 * NN];   // per-block column-sum slabs (2 MB)
static __device__ float  g_R[NB * NN];    // row sums of Tref per batch
static __device__ u64    g_sfx2[NN], g_sfy2[NN], g_sfyn2[NN];  // dup packed sf
static __device__ u64    g_twr2[1024], g_twi2[1024], g_twin2[1024]; // dup tw
static __device__ float  g_ctm[NN];       // column sums of spectrogram
static __device__ double g_smm;           // sum(Tmeas^2)
static __device__ int    g_maxbits;       // max(Tmeas) as int bits (values >= 0)
static __device__ double g_num[NB], g_smt[NB], g_stt[NB], g_den[NB];

// 5-bit bit reversal of a compile-time-constant p
#define BR5(p) ((((p)&1)<<4)|(((p)&2)<<2)|((p)&4)|(((p)&8)>>2)|(((p)&16)>>4))

// ---------------- packed f32x2 primitives ----------------
__device__ __forceinline__ u64 F2ADD(u64 a, u64 b) {
  u64 r; asm("add.rn.f32x2 %0,%1,%2;" : "=l"(r) : "l"(a), "l"(b)); return r;
}
__device__ __forceinline__ u64 F2MUL(u64 a, u64 b) {
  u64 r; asm("mul.rn.f32x2 %0,%1,%2;" : "=l"(r) : "l"(a), "l"(b)); return r;
}
__device__ __forceinline__ u64 F2FMA(u64 a, u64 b, u64 c) {
  u64 r; asm("fma.rn.f32x2 %0,%1,%2,%3;" : "=l"(r) : "l"(a), "l"(b), "l"(c)); return r;
}
__device__ __forceinline__ u64 PACK2(float lo, float hi) {
  u64 r; asm("mov.b64 %0,{%1,%2};" : "=l"(r) : "f"(lo), "f"(hi)); return r;
}
__device__ __forceinline__ float2 UNPK(u64 v) {
  float2 p; asm("mov.b64 {%0,%1},%2;" : "=f"(p.x), "=f"(p.y) : "l"(v)); return p;
}
#define DUP2(v) PACK2((v), (v))

// K[0] = (-1,-1); K[1..7] = +v1..v7; K[8..14] = -v1..-v7
// v1=0.19509  v2=0.38268  v3=0.55557  v4=0.70711  v5=0.83147  v6=0.92388  v7=0.98079
// sub via fma(b, K[0], a): exact
#define PBF1(i0,i1) { u64 ax=X[i0],ay=Y[i0],bx=X[i1],by=Y[i1];          \
  X[i0]=F2ADD(ax,bx); Y[i0]=F2ADD(ay,by);                               \
  X[i1]=F2FMA(bx,K[0],ax); Y[i1]=F2FMA(by,K[0],ay); }
#define PBFI(i0,i1) { u64 ax=X[i0],ay=Y[i0],bx=X[i1],by=Y[i1];          \
  X[i0]=F2ADD(ax,bx); Y[i0]=F2ADD(ay,by);                               \
  u64 dx=F2FMA(bx,K[0],ax), dy=F2FMA(by,K[0],ay);                       \
  X[i1]=dy; Y[i1]=F2MUL(dx,K[0]); }
// butterfly with twiddle (C - iS): C=K[IC], S=K[IS], -S=K[ISN]
#define PBFX(i0,i1,IC,IS,ISN) { u64 ax=X[i0],ay=Y[i0],bx=X[i1],by=Y[i1];\
  X[i0]=F2ADD(ax,bx); Y[i0]=F2ADD(ay,by);                               \
  u64 dx=F2FMA(bx,K[0],ax), dy=F2FMA(by,K[0],ay);                       \
  X[i1]=F2FMA(dy,K[IS],F2MUL(dx,K[IC]));                                \
  Y[i1]=F2FMA(dx,K[ISN],F2MUL(dy,K[IC])); }

__device__ __forceinline__ void fft32p(u64* X, u64* Y, const u64* K) {
  // stage h=16 : W32^j   (C,S) indices: +v=1..7, -v=8..14
  PBF1(0,16)
  PBFX(1,17, 7, 1, 8)
  PBFX(2,18, 6, 2, 9)
  PBFX(3,19, 5, 3,10)
  PBFX(4,20, 4, 4,11)
  PBFX(5,21, 3, 5,12)
  PBFX(6,22, 2, 6,13)
  PBFX(7,23, 1, 7,14)
  PBFI(8,24)
  PBFX(9,25,  8, 7,14)
  PBFX(10,26, 9, 6,13)
  PBFX(11,27,10, 5,12)
  PBFX(12,28,11, 4,11)
  PBFX(13,29,12, 3,10)
  PBFX(14,30,13, 2, 9)
  PBFX(15,31,14, 1, 8)
  // stage h=8 : W16^j
#pragma unroll
  for (int g = 0; g < 32; g += 16) {
    PBF1(g+0, g+8)
    PBFX(g+1, g+9,  6, 2, 9)
    PBFX(g+2, g+10, 4, 4,11)
    PBFX(g+3, g+11, 2, 6,13)
    PBFI(g+4, g+12)
    PBFX(g+5, g+13, 9, 6,13)
    PBFX(g+6, g+14,11, 4,11)
    PBFX(g+7, g+15,13, 2, 9)
  }
  // stage h=4 : W8^j
#pragma unroll
  for (int g = 0; g < 32; g += 8) {
    PBF1(g+0, g+4)
    PBFX(g+1, g+5, 4, 4,11)
    PBFI(g+2, g+6)
    PBFX(g+3, g+7,11, 4,11)
  }
#pragma unroll
  for (int g = 0; g < 32; g += 4) {
    PBF1(g+0, g+2)
    PBFI(g+1, g+3)
  }
#pragma unroll
  for (int g = 0; g < 32; g += 2) {
    PBF1(g, g+1)
  }
}

__device__ __forceinline__ float fsqrt_approx(float x) {
  float r;
  asm("sqrt.approx.f32 %0, %1;" : "=f"(r) : "f"(x));
  return r;
}

// ---------------- setup: tables + zero accumulators ----------------
__global__ void k_setup() {
  int gid = blockIdx.x * 64 + threadIdx.x;
  if (gid >= NN) return;
  const float c32 = (float)(2.0 * 337.927 * 1.5);   // fl32(1013.781)
  float t = c32 * (float)(gid - NN / 2);            // fp32 product (as jnp does)
  double s, c;
  sincos((double)t, &s, &c);
  float sfx = (float)(1.5 * c), sfy = (float)(-1.5 * s);
  g_sfx2[gid]  = DUP2(sfx);
  g_sfy2[gid]  = DUP2(sfy);
  g_sfyn2[gid] = DUP2(-sfy);
  {
    int ci = gid >> 5, lane = gid & 31;
    double th = (double)(ci * lane) * (6.283185307179586232e0 / 1024.0);
    double s2, c2;
    sincos(th, &s2, &c2);
    float wr = (float)c2, wi = (float)(-s2);
    g_twr2[gid]  = DUP2(wr);
    g_twi2[gid]  = DUP2(wi);
    g_twin2[gid] = DUP2(-wi);
  }
  g_ctm[gid] = 0.0f;
  if (gid < NB) { g_num[gid] = 0.0; g_smt[gid] = 0.0; g_stt[gid] = 0.0; g_den[gid] = 0.0; }
  if (gid == 0) { g_smm = 0.0; g_maxbits = 0; }
}

// ---------------- spectrogram stats: colsums, sum of squares, max ----------
__global__ void k_stats(const float* __restrict__ tm) {
  int tid = threadIdx.x;
  int r0 = blockIdx.x * 4;
  float c0 = 0.f, c1 = 0.f, c2 = 0.f, c3 = 0.f;
  float sq = 0.f, mx = 0.f;
#pragma unroll
  for (int r = r0; r < r0 + 4; ++r) {
    const float* rowp = tm + (size_t)r * NN;
    float v0 = rowp[tid];       float v1 = rowp[tid + 256];
    float v2 = rowp[tid + 512]; float v3 = rowp[tid + 768];
    c0 += v0; c1 += v1; c2 += v2; c3 += v3;
    sq = fmaf(v0, v0, sq); sq = fmaf(v1, v1, sq);
    sq = fmaf(v2, v2, sq); sq = fmaf(v3, v3, sq);
    mx = fmaxf(mx, fmaxf(fmaxf(v0, v1), fmaxf(v2, v3)));
  }
  atomicAdd(&g_ctm[tid      ], c0);
  atomicAdd(&g_ctm[tid + 256], c1);
  atomicAdd(&g_ctm[tid + 512], c2);
  atomicAdd(&g_ctm[tid + 768], c3);
#pragma unroll
  for (int o = 16; o; o >>= 1) {
    sq += __shfl_xor_sync(0xffffffffu, sq, o);
    mx = fmaxf(mx, __shfl_xor_sync(0xffffffffu, mx, o));
  }
  __shared__ float ssq[8], smx[8];
  int w = tid >> 5, l = tid & 31;
  if (l == 0) { ssq[w] = sq; smx[w] = mx; }
  __syncthreads();
  if (tid == 0) {
    float a = 0.f, b = 0.f;
#pragma unroll
    for (int i = 0; i < 8; ++i) { a += ssq[i]; b = fmaxf(b, smx[i]); }
    atomicAdd(&g_smm, (double)a);
    atomicMax(&g_maxbits, __float_as_int(b));
  }
}

// ---- main: 4 rows per warp as 2 packed pairs; table-fed f32x2 FFT ---------
__global__ void __launch_bounds__(128) k_main(const float* __restrict__ pred,
                                              const float* __restrict__ tmeas) {
  extern __shared__ u64 dsm[];
  u64* syxd  = dsm;          // [1024] (re[k], re[k])
  u64* syyd  = dsm + 1024;   // [1024] (im[k], im[k])
  u64* pairx = dsm + 2048;   // [1024] (re[k], re[k-1])
  u64* pairy = dsm + 3072;   // [1024] (im[k], im[k-1])
  u64* tbuf  = dsm + 4096;   // [4*1056] per-warp transpose
  int warp = threadIdx.x >> 5, lane = threadIdx.x & 31;
  int row0 = blockIdx.x * 16 + warp * 4;  // first of 4 rows for this warp
  int b = row0 >> 10;
  const float* pb = pred + b * 2 * NN;

  for (int i = threadIdx.x; i < NN; i += 128) {
    float re = pb[i], im = pb[NN + i];
    int km = (i - 1) & (NN - 1);
    float rem = pb[km], imm = pb[NN + km];
    syxd[i]  = PACK2(re, re);
    syyd[i]  = PACK2(im, im);
    pairx[i] = PACK2(re, rem);
    pairy[i] = PACK2(im, imm);
  }
  __syncthreads();

  // packed butterfly constants, hoisted once
  u64 K[15];
  K[0] = DUP2(-1.0f);
  K[1] = DUP2(0.19509032201612825f);  K[8]  = DUP2(-0.19509032201612825f);
  K[2] = DUP2(0.38268343236508978f);  K[9]  = DUP2(-0.38268343236508978f);
  K[3] = DUP2(0.55557023301960218f);  K[10] = DUP2(-0.55557023301960218f);
  K[4] = DUP2(0.70710678118654757f);  K[11] = DUP2(-0.70710678118654757f);
  K[5] = DUP2(0.83146961230254524f);  K[12] = DUP2(-0.83146961230254524f);
  K[6] = DUP2(0.92387953251128674f);  K[13] = DUP2(-0.92387953251128674f);
  K[7] = DUP2(0.98078528040323043f);  K[14] = DUP2(-0.98078528040323043f);

  u64* tb = tbuf + warp * 1056;

  float csum[32];
#pragma unroll
  for (int p = 0; p < 32; ++p) csum[p] = 0.f;
  float stt = 0.f, smt = 0.f;

#pragma unroll 1
  for (int t = 0; t < 2; ++t) {
    int m0 = (row0 & (NN - 1)) + 2 * t;   // rows m0 (lo), m0+1 (hi) packed
    int d0 = m0 - NN / 2;

    u64 X[32], Y[32];
    // prod[j] = 1.5 * y[j] * y[(j-delay)&1023] * sf[j], packed over 2 rows
#pragma unroll
    for (int a = 0; a < 32; ++a) {
      int j = a * 32 + lane;
      int j0 = (j - d0) & (NN - 1);       // hi-row gather is j0-1 => pair table
      u64 yax = syxd[j], yay = syyd[j];
      u64 ybx = pairx[j0], yby = pairy[j0];
      u64 sfx = g_sfx2[j], sfy = g_sfy2[j], sfyn = g_sfyn2[j];
      u64 nyay = F2MUL(yay, K[0]);
      u64 prr = F2FMA(nyay, yby, F2MUL(yax, ybx));
      u64 pri = F2FMA(yay,  ybx, F2MUL(yax, yby));
      X[a] = F2FMA(pri, sfyn, F2MUL(prr, sfx));
      Y[a] = F2FMA(pri, sfx,  F2MUL(prr, sfy));
    }
    // step 1: FFT32 over a  ->  reg p holds Y[BR5(p), col=lane]
    fft32p(X, Y, K);

    // step 2: twiddle by exp(-2*pi*i * lane * c / 1024), c = BR5(p)
#pragma unroll
    for (int c = 0; c < 32; ++c) {
      int p = BR5(c);
      u64 wr  = g_twr2[c * 32 + lane];
      u64 wi  = g_twi2[c * 32 + lane];
      u64 win = g_twin2[c * 32 + lane];
      u64 x = X[p], y = Y[p];
      X[p] = F2FMA(y, win, F2MUL(x, wr));
      Y[p] = F2FMA(y, wr,  F2MUL(x, wi));
    }

    // transpose via padded shared, packed u64, two passes (X then Y)
#pragma unroll
    for (int p = 0; p < 32; ++p) tb[BR5(p) * 33 + lane] = X[p];
    __syncwarp();
#pragma unroll
    for (int bb = 0; bb < 32; ++bb) X[bb] = tb[lane * 33 + bb];
    __syncwarp();
#pragma unroll
    for (int p = 0; p < 32; ++p) tb[BR5(p) * 33 + lane] = Y[p];
    __syncwarp();
#pragma unroll
    for (int bb = 0; bb < 32; ++bb) Y[bb] = tb[lane * 33 + bb];
    __syncwarp();

    // step 3: FFT32 over b -> reg p holds Xf[lane + 32*BR5(p)]
    fft32p(X, Y, K);

    // Tref[m][col] = |Xf|, col = lane + ((BR5(p)^16)<<5)
    float rsum0 = 0.f, rsum1 = 0.f;
    const float* tmr0 = tmeas + (size_t)m0 * NN;
    const float* tmr1 = tmr0 + NN;
#pragma unroll
    for (int p = 0; p < 32; ++p) {
      int col = lane + ((BR5(p) ^ 16) << 5);
      float2 xs = UNPK(X[p]), ys = UNPK(Y[p]);
      float m0v = fsqrt_approx(fmaf(xs.x, xs.x, ys.x * ys.x));
      float m1v = fsqrt_approx(fmaf(xs.y, xs.y, ys.y * ys.y));
      csum[p] += m0v + m1v;
      rsum0 += m0v; rsum1 += m1v;
      stt = fmaf(m0v, m0v, stt); stt = fmaf(m1v, m1v, stt);
      smt = fmaf(tmr0[col], m0v, smt); smt = fmaf(tmr1[col], m1v, smt);
    }
#pragma unroll
    for (int o = 16; o; o >>= 1) {
      rsum0 += __shfl_xor_sync(0xffffffffu, rsum0, o);
      rsum1 += __shfl_xor_sync(0xffffffffu, rsum1, o);
    }
    if (lane == 0) {
      g_R[row0 + 2 * t    ] = rsum0;
      g_R[row0 + 2 * t + 1] = rsum1;
    }
  }

#pragma unroll
  for (int o = 16; o; o >>= 1) {
    stt += __shfl_xor_sync(0xffffffffu, stt, o);
    smt += __shfl_xor_sync(0xffffffffu, smt, o);
  }
  if (lane == 0) {
    atomicAdd(&g_smt[b], (double)smt);
    atomicAdd(&g_stt[b], (double)stt);
  }

  // combine 4 warps' column sums -> one slab per block (no atomics)
  __syncthreads();                        // all warps done with transpose bufs
  float* sflat = (float*)tbuf;            // need 4096 floats, have 8448
#pragma unroll
  for (int p = 0; p < 32; ++p) {
    int col = lane + ((BR5(p) ^ 16) << 5);
    sflat[warp * 1024 + col] = csum[p];
  }
  __syncthreads();
  float* slab = g_S + (size_t)blockIdx.x * NN;
#pragma unroll
  for (int k = 0; k < 8; ++k) {
    int col = threadIdx.x + 128 * k;
    slab[col] = sflat[col] + sflat[1024 + col] + sflat[2048 + col] + sflat[3072 + col];
  }
}

// ---- den[b] = sum over slabs of dot(slab, R[b]);  num[b] = dot(ctm, R[b]) -
__global__ void k_red() {
  int i = blockIdx.x;                     // 1024 blocks: half slab each
  int slab = i >> 1, half = (i & 1) * 512;
  int b = slab >> 6;
  int tid = threadIdx.x;                  // 128 threads
  const float* Rp = g_R + b * NN + half;
  const float* sp = g_S + (size_t)slab * NN + half;

  float sden = 0.f, snum = 0.f;
#pragma unroll
  for (int q = 0; q < 4; ++q) {
    int cidx = tid + 128 * q;
    sden = fmaf(sp[cidx], Rp[cidx], sden);
  }
  if ((slab & 63) == 0) {
    const float* cp = g_ctm + half;
#pragma unroll
    for (int q = 0; q < 4; ++q) {
      int cidx = tid + 128 * q;
      snum = fmaf(cp[cidx], Rp[cidx], snum);
    }
  }
#pragma unroll
  for (int o = 16; o; o >>= 1) {
    sden += __shfl_xor_sync(0xffffffffu, sden, o);
    snum += __shfl_xor_sync(0xffffffffu, snum, o);
  }
  __shared__ float wd[4], wn[4];
  int w = tid >> 5, l = tid & 31;
  if (l == 0) { wd[w] = sden; wn[w] = snum; }
  __syncthreads();
  if (tid == 0) {
    float a = wd[0] + wd[1] + wd[2] + wd[3];
    float c = wn[0] + wn[1] + wn[2] + wn[3];
    atomicAdd(&g_den[b], (double)a);
    if ((slab & 63) == 0) atomicAdd(&g_num[b], (double)c);
  }
}

// ---------------- finalize scalar ----------------
__global__ void k_final(float* __restrict__ out) {
  if (threadIdx.x == 0 && blockIdx.x == 0) {
    float mx = __int_as_float(g_maxbits);
    double norm = 1048576.0 * (double)mx * (double)mx;
    double acc = 0.0;
#pragma unroll
    for (int b = 0; b < NB; ++b) {
      double mu = g_num[b] / g_den[b];
      double r = g_smm - 2.0 * mu * g_smt[b] + mu * mu * g_stt[b];
      if (r < 0.0) r = 0.0;
      acc += sqrt(r / norm);
    }
    out[0] = (float)(acc / (double)NB);
  }
}

extern "C" void kernel_launch(void* const* d_in, const int* in_sizes, int n_in,
                              void* d_out, int out_size) {
  const float* pred  = (const float*)d_in[0];   // [8, 2048]
  // d_in[1] = label, unused by the reference loss
  const float* tmeas = (const float*)d_in[2];   // [1024, 1024]
  (void)in_sizes; (void)n_in; (void)out_size;

  const int dsm_bytes = (4096 + 4 * 1056) * sizeof(u64);   // 66560
  static int attr_set = 0;
  if (!attr_set) {
    cudaFuncSetAttribute(k_main, cudaFuncAttributeMaxDynamicSharedMemorySize,
                         dsm_bytes);
    attr_set = 1;
  }

  k_setup<<<16, 64>>>();
  k_stats<<<256, 256>>>(tmeas);
  k_main<<<512, 128, dsm_bytes>>>(pred, tmeas);
  k_red<<<1024, 128>>>();
  k_final<<<1, 32>>>((float*)d_out);
}

// round 8
// speedup vs baseline: 1.0748x; 1.0748x over previous
#include <cuda_runtime.h>

#define NN 1024
#define NB 8

// ---------------- scratch (static device globals: allowed) ----------------
// Zero-initialized at module load; k_final's tail resets them after each run.
static __device__ float  g_C[NB * NN];    // per-batch Tref column sums
static __device__ float  g_R[NB * NN];    // per-batch Tref row sums
static __device__ float2 g_sf[NN];        // 1.5 * shift factor per element j
static __device__ float2 g_twtab[32 * 32];// twtab[c*32+lane] = exp(-2pi i lane c/1024)
static __device__ float  g_ctm[NN];       // column sums of spectrogram
static __device__ double g_smm;           // sum(Tmeas^2)
static __device__ int    g_maxbits;       // max(Tmeas) as int bits (values >= 0)
static __device__ double g_num[NB], g_smt[NB], g_stt[NB], g_den[NB];

// 5-bit bit reversal of a compile-time-constant p
#define BR5(p) ((((p)&1)<<4)|(((p)&2)<<2)|((p)&4)|(((p)&8)>>2)|(((p)&16)>>4))

// ---------------- register FFT32 (DIF, natural in, bit-reversed out) -------
#define BF(i0,i1,C,S) { float ax=vx[i0],ay=vy[i0],bx=vx[i1],by=vy[i1]; \
  vx[i0]=ax+bx; vy[i0]=ay+by; float dx=ax-bx,dy=ay-by;                 \
  vx[i1]=fmaf(dy,(S),dx*(C)); vy[i1]=fmaf(-dx,(S),dy*(C)); }
#define BF1(i0,i1) { float ax=vx[i0],ay=vy[i0],bx=vx[i1],by=vy[i1];    \
  vx[i0]=ax+bx; vy[i0]=ay+by; vx[i1]=ax-bx; vy[i1]=ay-by; }
#define BFI(i0,i1) { float ax=vx[i0],ay=vy[i0],bx=vx[i1],by=vy[i1];    \
  vx[i0]=ax+bx; vy[i0]=ay+by; float dx=ax-bx,dy=ay-by;                 \
  vx[i1]=dy; vy[i1]=-dx; }

__device__ __forceinline__ void fft32(float vx[32], float vy[32]) {
  BF1(0,16)
  BF(1,17, 0.98078528040323043f, 0.19509032201612825f)
  BF(2,18, 0.92387953251128674f, 0.38268343236508978f)
  BF(3,19, 0.83146961230254524f, 0.55557023301960218f)
  BF(4,20, 0.70710678118654757f, 0.70710678118654757f)
  BF(5,21, 0.55557023301960218f, 0.83146961230254524f)
  BF(6,22, 0.38268343236508978f, 0.92387953251128674f)
  BF(7,23, 0.19509032201612825f, 0.98078528040323043f)
  BFI(8,24)
  BF(9,25, -0.19509032201612825f, 0.98078528040323043f)
  BF(10,26,-0.38268343236508978f, 0.92387953251128674f)
  BF(11,27,-0.55557023301960218f, 0.83146961230254524f)
  BF(12,28,-0.70710678118654757f, 0.70710678118654757f)
  BF(13,29,-0.83146961230254524f, 0.55557023301960218f)
  BF(14,30,-0.92387953251128674f, 0.38268343236508978f)
  BF(15,31,-0.98078528040323043f, 0.19509032201612825f)
#pragma unroll
  for (int g = 0; g < 32; g += 16) {
    BF1(g+0, g+8)
    BF(g+1, g+9,  0.92387953251128674f, 0.38268343236508978f)
    BF(g+2, g+10, 0.70710678118654757f, 0.70710678118654757f)
    BF(g+3, g+11, 0.38268343236508978f, 0.92387953251128674f)
    BFI(g+4, g+12)
    BF(g+5, g+13,-0.38268343236508978f, 0.92387953251128674f)
    BF(g+6, g+14,-0.70710678118654757f, 0.70710678118654757f)
    BF(g+7, g+15,-0.92387953251128674f, 0.38268343236508978f)
  }
#pragma unroll
  for (int g = 0; g < 32; g += 8) {
    BF1(g+0, g+4)
    BF(g+1, g+5,  0.70710678118654757f, 0.70710678118654757f)
    BFI(g+2, g+6)
    BF(g+3, g+7, -0.70710678118654757f, 0.70710678118654757f)
  }
#pragma unroll
  for (int g = 0; g < 32; g += 4) {
    BF1(g+0, g+2)
    BFI(g+1, g+3)
  }
#pragma unroll
  for (int g = 0; g < 32; g += 2) {
    BF1(g, g+1)
  }
}

__device__ __forceinline__ float fsqrt_approx(float x) {
  float r;
  asm("sqrt.approx.f32 %0, %1;" : "=f"(r) : "f"(x));
  return r;
}

// ------- fused: spectrogram stats (blocks 0-255) + table setup (256-259) ---
// Accumulators (g_ctm, g_smm, g_maxbits) are pre-zeroed: module load for the
// first call, k_final's tail for every subsequent call. No zeroing here -> no
// intra-kernel init/accumulate race.
__global__ void k_prep(const float* __restrict__ tm) {
  int tid = threadIdx.x;
  if (blockIdx.x >= 256) {
    // ---- table setup path (idempotent writes only) ----
    int gid = (blockIdx.x - 256) * 256 + tid;   // 0..1023
    const float c32 = (float)(2.0 * 337.927 * 1.5);   // fl32(1013.781)
    float t = c32 * (float)(gid - NN / 2);            // fp32 product (as jnp)
    double s, c;
    sincos((double)t, &s, &c);
    g_sf[gid] = make_float2((float)(1.5 * c), (float)(-1.5 * s));
    {
      int ci = gid >> 5, lane = gid & 31;
      double th = (double)(ci * lane) * (6.283185307179586232e0 / 1024.0);
      double s2, c2;
      sincos(th, &s2, &c2);
      g_twtab[gid] = make_float2((float)c2, (float)(-s2));
    }
    return;
  }
  // ---- stats path: colsums, sum of squares, max over 4 rows ----
  int r0 = blockIdx.x * 4;
  float c0 = 0.f, c1 = 0.f, c2 = 0.f, c3 = 0.f;
  float sq = 0.f, mx = 0.f;
#pragma unroll
  for (int r = r0; r < r0 + 4; ++r) {
    const float* rowp = tm + (size_t)r * NN;
    float v0 = rowp[tid];       float v1 = rowp[tid + 256];
    float v2 = rowp[tid + 512]; float v3 = rowp[tid + 768];
    c0 += v0; c1 += v1; c2 += v2; c3 += v3;
    sq = fmaf(v0, v0, sq); sq = fmaf(v1, v1, sq);
    sq = fmaf(v2, v2, sq); sq = fmaf(v3, v3, sq);
    mx = fmaxf(mx, fmaxf(fmaxf(v0, v1), fmaxf(v2, v3)));
  }
  atomicAdd(&g_ctm[tid      ], c0);
  atomicAdd(&g_ctm[tid + 256], c1);
  atomicAdd(&g_ctm[tid + 512], c2);
  atomicAdd(&g_ctm[tid + 768], c3);
#pragma unroll
  for (int o = 16; o; o >>= 1) {
    sq += __shfl_xor_sync(0xffffffffu, sq, o);
    mx = fmaxf(mx, __shfl_xor_sync(0xffffffffu, mx, o));
  }
  __shared__ float ssq[8], smx[8];
  int w = tid >> 5, l = tid & 31;
  if (l == 0) { ssq[w] = sq; smx[w] = mx; }
  __syncthreads();
  if (tid == 0) {
    float a = 0.f, b = 0.f;
#pragma unroll
    for (int i = 0; i < 8; ++i) { a += ssq[i]; b = fmaxf(b, smx[i]); }
    atomicAdd(&g_smm, (double)a);
    atomicMax(&g_maxbits, __float_as_int(b));
  }
}

// ---- main: 2 rows per warp, fused prod + FFT1024 + |.| + block colsums ----
__global__ void __launch_bounds__(128) k_main(const float* __restrict__ pred,
                                              const float* __restrict__ tmeas) {
  __shared__ float2 sh2[4 * 1056];        // per-warp 32x33 complex transpose buf
  __shared__ float2 sy2[NN];              // batch analytic signal, interleaved
  int warp = threadIdx.x >> 5, lane = threadIdx.x & 31;
  int row0 = blockIdx.x * 8 + warp * 2;   // first of 2 rows for this warp
  int b = row0 >> 10;

  // stage this batch's y into shared, interleaved (re, im)
  for (int i = threadIdx.x; i < NN; i += 128)
    sy2[i] = make_float2(pred[b * 2 * NN + i], pred[b * 2 * NN + NN + i]);
  __syncthreads();

  float2* tb = sh2 + warp * 1056;

  float csum[32];
#pragma unroll
  for (int p = 0; p < 32; ++p) csum[p] = 0.f;
  float stt = 0.f, smt = 0.f;

#pragma unroll 1
  for (int r = 0; r < 2; ++r) {
    int m = (row0 & (NN - 1)) + r;
    int delay = m - NN / 2;

    float vx[32], vy[32];
    // prod[j] = 1.5 * y[j] * y[(j-delay)&1023] * sf[j],  j = 32a + lane
#pragma unroll
    for (int a = 0; a < 32; ++a) {
      int j = a * 32 + lane;
      int jj = (j - delay) & (NN - 1);
      float2 ya = sy2[j];
      float2 yb = sy2[jj];
      float2 sf = g_sf[j];
      float prr = ya.x * yb.x - ya.y * yb.y;
      float pri = ya.x * yb.y + ya.y * yb.x;
      vx[a] = prr * sf.x - pri * sf.y;
      vy[a] = prr * sf.y + pri * sf.x;
    }
    // step 1: FFT32 over a  ->  reg p holds Y[BR5(p), col=lane]
    fft32(vx, vy);

    // step 2: twiddle by exp(-2*pi*i * lane * c / 1024), c = BR5(p)
#pragma unroll
    for (int c = 0; c < 32; ++c) {
      int p = BR5(c);
      float2 w = g_twtab[c * 32 + lane];
      float x = vx[p], y = vy[p];
      vx[p] = x * w.x - y * w.y;
      vy[p] = x * w.y + y * w.x;
    }

    // transpose via padded shared, 64-bit accesses (absorbs bit-reversal)
#pragma unroll
    for (int p = 0; p < 32; ++p) {
      int c = BR5(p);
      tb[c * 33 + lane] = make_float2(vx[p], vy[p]);
    }
    __syncwarp();
#pragma unroll
    for (int bb = 0; bb < 32; ++bb) {
      float2 t = tb[lane * 33 + bb];
      vx[bb] = t.x; vy[bb] = t.y;
    }
    __syncwarp();   // buffer reused next row
    // step 3: FFT32 over b -> reg p holds X[lane + 32*BR5(p)]
    fft32(vx, vy);

    // Tref[m][col] = |X|, col = lane + ((BR5(p)^16)<<5)  (scale pre-folded)
    float rsum = 0.f;
    const float* tmr = tmeas + (size_t)m * NN;
#pragma unroll
    for (int p = 0; p < 32; ++p) {
      int col = lane + ((BR5(p) ^ 16) << 5);
      float mag = fsqrt_approx(fmaf(vx[p], vx[p], vy[p] * vy[p]));
      csum[p] += mag;
      rsum += mag;
      stt = fmaf(mag, mag, stt);
      smt = fmaf(tmr[col], mag, smt);
    }
#pragma unroll
    for (int o = 16; o; o >>= 1)
      rsum += __shfl_xor_sync(0xffffffffu, rsum, o);
    if (lane == 0) g_R[row0 + r] = rsum;
  }

#pragma unroll
  for (int o = 16; o; o >>= 1) {
    stt += __shfl_xor_sync(0xffffffffu, stt, o);
    smt += __shfl_xor_sync(0xffffffffu, smt, o);
  }
  if (lane == 0) {
    atomicAdd(&g_smt[b], (double)smt);
    atomicAdd(&g_stt[b], (double)stt);
  }

  // combine 4 warps' column sums in shared, then one atomic add per column
  __syncthreads();                        // all warps done with transpose bufs
  float* sflat = (float*)sh2;             // need 4096 floats, have 8448
#pragma unroll
  for (int p = 0; p < 32; ++p) {
    int col = lane + ((BR5(p) ^ 16) << 5);
    sflat[warp * 1024 + col] = csum[p];
  }
  __syncthreads();
  float* cb = g_C + b * NN;
#pragma unroll
  for (int k = 0; k < 8; ++k) {
    int col = threadIdx.x + 128 * k;
    float v = sflat[col] + sflat[1024 + col] + sflat[2048 + col] + sflat[3072 + col];
    atomicAdd(&cb[col], v);               // RED.F32, 8K addresses, low contention
  }
}

// ---- den[b] = dot(C[b], R[b]);  num[b] = dot(ctm, R[b]) -------------------
__global__ void k_red() {
  int b = blockIdx.x;                     // 8 blocks, 1024 threads
  int tid = threadIdx.x;
  float r = g_R[b * NN + tid];
  float sden = g_C[b * NN + tid] * r;
  float snum = g_ctm[tid] * r;
#pragma unroll
  for (int o = 16; o; o >>= 1) {
    sden += __shfl_xor_sync(0xffffffffu, sden, o);
    snum += __shfl_xor_sync(0xffffffffu, snum, o);
  }
  __shared__ float wd[32], wn[32];
  int w = tid >> 5, l = tid & 31;
  if (l == 0) { wd[w] = sden; wn[w] = snum; }
  __syncthreads();
  if (w == 0) {
    float a = wd[l], c = wn[l];
#pragma unroll
    for (int o = 16; o; o >>= 1) {
      a += __shfl_xor_sync(0xffffffffu, a, o);
      c += __shfl_xor_sync(0xffffffffu, c, o);
    }
    if (l == 0) { g_den[b] = (double)a; g_num[b] = (double)c; }
  }
}

// ------- finalize scalar, then reset accumulators for the next replay ------
__global__ void k_final(float* __restrict__ out) {
  int tid = threadIdx.x;                  // 1024 threads, 1 block
  if (tid == 0) {
    float mx = __int_as_float(g_maxbits);
    double norm = 1048576.0 * (double)mx * (double)mx;
    double acc = 0.0;
#pragma unroll
    for (int b = 0; b < NB; ++b) {
      double mu = g_num[b] / g_den[b];
      double r = g_smm - 2.0 * mu * g_smt[b] + mu * mu * g_stt[b];
      if (r < 0.0) r = 0.0;
      acc += sqrt(r / norm);
    }
    out[0] = (float)(acc / (double)NB);
  }
  __syncthreads();                        // output computed before reset
#pragma unroll
  for (int i = 0; i < NB; ++i) g_C[tid + i * NN] = 0.0f;
  g_ctm[tid] = 0.0f;
  if (tid < NB) { g_smt[tid] = 0.0; g_stt[tid] = 0.0; }
  if (tid == 0) { g_smm = 0.0; g_maxbits = 0; }
}

extern "C" void kernel_launch(void* const* d_in, const int* in_sizes, int n_in,
                              void* d_out, int out_size) {
  const float* pred  = (const float*)d_in[0];   // [8, 2048]
  // d_in[1] = label, unused by the reference loss
  const float* tmeas = (const float*)d_in[2];   // [1024, 1024]
  (void)in_sizes; (void)n_in; (void)out_size;

  k_prep<<<260, 256>>>(tmeas);
  k_main<<<1024, 128>>>(pred, tmeas);
  k_red<<<NB, 1024>>>();
  k_final<<<1, 1024>>>((float*)d_out);
}

// round 9
// speedup vs baseline: 1.2873x; 1.1977x over previous
#include <cuda_runtime.h>

#define NN 1024
#define NB 8

// ---------------- scratch (static device globals: allowed) ----------------
// Zero-initialized at module load; k_final's tail resets them after each run.
static __device__ float  g_C[NB * NN];    // per-batch Tref column sums
static __device__ float  g_R[NB * NN];    // per-batch Tref row sums
static __device__ float2 g_sf[NN];        // 1.5 * shift factor per element j
static __device__ float2 g_twtab[32 * 32];// twtab[c*32+lane] = exp(-2pi i lane c/1024)
static __device__ float  g_ctm[NN];       // column sums of spectrogram
static __device__ double g_smm;           // sum(Tmeas^2)
static __device__ int    g_maxbits;       // max(Tmeas) as int bits (values >= 0)
static __device__ double g_num[NB], g_smt[NB], g_stt[NB], g_den[NB];

// 5-bit bit reversal of a compile-time-constant p
#define BR5(p) ((((p)&1)<<4)|(((p)&2)<<2)|((p)&4)|(((p)&8)>>2)|(((p)&16)>>4))

// ---------------- register FFT32 (DIF, natural in, bit-reversed out) -------
#define BF(i0,i1,C,S) { float ax=vx[i0],ay=vy[i0],bx=vx[i1],by=vy[i1]; \
  vx[i0]=ax+bx; vy[i0]=ay+by; float dx=ax-bx,dy=ay-by;                 \
  vx[i1]=fmaf(dy,(S),dx*(C)); vy[i1]=fmaf(-dx,(S),dy*(C)); }
#define BF1(i0,i1) { float ax=vx[i0],ay=vy[i0],bx=vx[i1],by=vy[i1];    \
  vx[i0]=ax+bx; vy[i0]=ay+by; vx[i1]=ax-bx; vy[i1]=ay-by; }
#define BFI(i0,i1) { float ax=vx[i0],ay=vy[i0],bx=vx[i1],by=vy[i1];    \
  vx[i0]=ax+bx; vy[i0]=ay+by; float dx=ax-bx,dy=ay-by;                 \
  vx[i1]=dy; vy[i1]=-dx; }

__device__ __forceinline__ void fft32(float vx[32], float vy[32]) {
  BF1(0,16)
  BF(1,17, 0.98078528040323043f, 0.19509032201612825f)
  BF(2,18, 0.92387953251128674f, 0.38268343236508978f)
  BF(3,19, 0.83146961230254524f, 0.55557023301960218f)
  BF(4,20, 0.70710678118654757f, 0.70710678118654757f)
  BF(5,21, 0.55557023301960218f, 0.83146961230254524f)
  BF(6,22, 0.38268343236508978f, 0.92387953251128674f)
  BF(7,23, 0.19509032201612825f, 0.98078528040323043f)
  BFI(8,24)
  BF(9,25, -0.19509032201612825f, 0.98078528040323043f)
  BF(10,26,-0.38268343236508978f, 0.92387953251128674f)
  BF(11,27,-0.55557023301960218f, 0.83146961230254524f)
  BF(12,28,-0.70710678118654757f, 0.70710678118654757f)
  BF(13,29,-0.83146961230254524f, 0.55557023301960218f)
  BF(14,30,-0.92387953251128674f, 0.38268343236508978f)
  BF(15,31,-0.98078528040323043f, 0.19509032201612825f)
#pragma unroll
  for (int g = 0; g < 32; g += 16) {
    BF1(g+0, g+8)
    BF(g+1, g+9,  0.92387953251128674f, 0.38268343236508978f)
    BF(g+2, g+10, 0.70710678118654757f, 0.70710678118654757f)
    BF(g+3, g+11, 0.38268343236508978f, 0.92387953251128674f)
    BFI(g+4, g+12)
    BF(g+5, g+13,-0.38268343236508978f, 0.92387953251128674f)
    BF(g+6, g+14,-0.70710678118654757f, 0.70710678118654757f)
    BF(g+7, g+15,-0.92387953251128674f, 0.38268343236508978f)
  }
#pragma unroll
  for (int g = 0; g < 32; g += 8) {
    BF1(g+0, g+4)
    BF(g+1, g+5,  0.70710678118654757f, 0.70710678118654757f)
    BFI(g+2, g+6)
    BF(g+3, g+7, -0.70710678118654757f, 0.70710678118654757f)
  }
#pragma unroll
  for (int g = 0; g < 32; g += 4) {
    BF1(g+0, g+2)
    BFI(g+1, g+3)
  }
#pragma unroll
  for (int g = 0; g < 32; g += 2) {
    BF1(g, g+1)
  }
}

__device__ __forceinline__ float fsqrt_approx(float x) {
  float r;
  asm("sqrt.approx.f32 %0, %1;" : "=f"(r) : "f"(x));
  return r;
}

// ------- fused: spectrogram stats (blocks 0-255) + table setup (256-259) ---
// Accumulators (g_ctm, g_smm, g_maxbits) are pre-zeroed: module load for the
// first call, k_final's tail for every subsequent call. No zeroing here -> no
// intra-kernel init/accumulate race.
__global__ void k_prep(const float* __restrict__ tm) {
  int tid = threadIdx.x;
  if (blockIdx.x >= 256) {
    // ---- table setup path (idempotent writes only) ----
    int gid = (blockIdx.x - 256) * 256 + tid;   // 0..1023
    const float c32 = (float)(2.0 * 337.927 * 1.5);   // fl32(1013.781)
    float t = c32 * (float)(gid - NN / 2);            // fp32 product (as jnp)
    double s, c;
    sincos((double)t, &s, &c);
    g_sf[gid] = make_float2((float)(1.5 * c), (float)(-1.5 * s));
    {
      int ci = gid >> 5, lane = gid & 31;
      double th = (double)(ci * lane) * (6.283185307179586232e0 / 1024.0);
      double s2, c2;
      sincos(th, &s2, &c2);
      g_twtab[gid] = make_float2((float)c2, (float)(-s2));
    }
    return;
  }
  // ---- stats path: colsums, sum of squares, max over 4 rows ----
  int r0 = blockIdx.x * 4;
  float c0 = 0.f, c1 = 0.f, c2 = 0.f, c3 = 0.f;
  float sq = 0.f, mx = 0.f;
#pragma unroll
  for (int r = r0; r < r0 + 4; ++r) {
    const float* rowp = tm + (size_t)r * NN;
    float v0 = rowp[tid];       float v1 = rowp[tid + 256];
    float v2 = rowp[tid + 512]; float v3 = rowp[tid + 768];
    c0 += v0; c1 += v1; c2 += v2; c3 += v3;
    sq = fmaf(v0, v0, sq); sq = fmaf(v1, v1, sq);
    sq = fmaf(v2, v2, sq); sq = fmaf(v3, v3, sq);
    mx = fmaxf(mx, fmaxf(fmaxf(v0, v1), fmaxf(v2, v3)));
  }
  atomicAdd(&g_ctm[tid      ], c0);
  atomicAdd(&g_ctm[tid + 256], c1);
  atomicAdd(&g_ctm[tid + 512], c2);
  atomicAdd(&g_ctm[tid + 768], c3);
#pragma unroll
  for (int o = 16; o; o >>= 1) {
    sq += __shfl_xor_sync(0xffffffffu, sq, o);
    mx = fmaxf(mx, __shfl_xor_sync(0xffffffffu, mx, o));
  }
  __shared__ float ssq[8], smx[8];
  int w = tid >> 5, l = tid & 31;
  if (l == 0) { ssq[w] = sq; smx[w] = mx; }
  __syncthreads();
  if (tid == 0) {
    float a = 0.f, b = 0.f;
#pragma unroll
    for (int i = 0; i < 8; ++i) { a += ssq[i]; b = fmaxf(b, smx[i]); }
    atomicAdd(&g_smm, (double)a);
    atomicMax(&g_maxbits, __float_as_int(b));
  }
}

// ---- main: 2 rows per warp, fused prod + FFT1024 + |.| + block colsums ----
__global__ void __launch_bounds__(128) k_main(const float* __restrict__ pred,
                                              const float* __restrict__ tmeas) {
  __shared__ float2 sh2[4 * 1056];        // per-warp 32x33 complex transpose buf
  __shared__ float2 sy2[NN];              // batch analytic signal, interleaved
  int warp = threadIdx.x >> 5, lane = threadIdx.x & 31;
  int row0 = blockIdx.x * 8 + warp * 2;   // first of 2 rows for this warp
  int b = row0 >> 10;

  // stage this batch's y into shared, interleaved (re, im)
  for (int i = threadIdx.x; i < NN; i += 128)
    sy2[i] = make_float2(pred[b * 2 * NN + i], pred[b * 2 * NN + NN + i]);
  __syncthreads();

  float2* tb = sh2 + warp * 1056;

  float csum[32];
#pragma unroll
  for (int p = 0; p < 32; ++p) csum[p] = 0.f;
  float stt = 0.f, smt = 0.f;

#pragma unroll 1
  for (int r = 0; r < 2; ++r) {
    int m = (row0 & (NN - 1)) + r;
    int delay = m - NN / 2;

    float vx[32], vy[32];
    // prod[j] = 1.5 * y[j] * y[(j-delay)&1023] * sf[j],  j = 32a + lane
#pragma unroll
    for (int a = 0; a < 32; ++a) {
      int j = a * 32 + lane;
      int jj = (j - delay) & (NN - 1);
      float2 ya = sy2[j];
      float2 yb = sy2[jj];
      float2 sf = g_sf[j];
      float prr = ya.x * yb.x - ya.y * yb.y;
      float pri = ya.x * yb.y + ya.y * yb.x;
      vx[a] = prr * sf.x - pri * sf.y;
      vy[a] = prr * sf.y + pri * sf.x;
    }
    // step 1: FFT32 over a  ->  reg p holds Y[BR5(p), col=lane]
    fft32(vx, vy);

    // step 2: twiddle by exp(-2*pi*i * lane * c / 1024), c = BR5(p)
#pragma unroll
    for (int c = 0; c < 32; ++c) {
      int p = BR5(c);
      float2 w = g_twtab[c * 32 + lane];
      float x = vx[p], y = vy[p];
      vx[p] = x * w.x - y * w.y;
      vy[p] = x * w.y + y * w.x;
    }

    // transpose via padded shared, 64-bit accesses (absorbs bit-reversal)
#pragma unroll
    for (int p = 0; p < 32; ++p) {
      int c = BR5(p);
      tb[c * 33 + lane] = make_float2(vx[p], vy[p]);
    }
    __syncwarp();
#pragma unroll
    for (int bb = 0; bb < 32; ++bb) {
      float2 t = tb[lane * 33 + bb];
      vx[bb] = t.x; vy[bb] = t.y;
    }
    __syncwarp();   // buffer reused next row
    // step 3: FFT32 over b -> reg p holds X[lane + 32*BR5(p)]
    fft32(vx, vy);

    // Tref[m][col] = |X|, col = lane + ((BR5(p)^16)<<5)  (scale pre-folded)
    float rsum = 0.f;
    const float* tmr = tmeas + (size_t)m * NN;
#pragma unroll
    for (int p = 0; p < 32; ++p) {
      int col = lane + ((BR5(p) ^ 16) << 5);
      float mag = fsqrt_approx(fmaf(vx[p], vx[p], vy[p] * vy[p]));
      csum[p] += mag;
      rsum += mag;
      stt = fmaf(mag, mag, stt);
      smt = fmaf(tmr[col], mag, smt);
    }
#pragma unroll
    for (int o = 16; o; o >>= 1)
      rsum += __shfl_xor_sync(0xffffffffu, rsum, o);
    if (lane == 0) g_R[row0 + r] = rsum;
  }

#pragma unroll
  for (int o = 16; o; o >>= 1) {
    stt += __shfl_xor_sync(0xffffffffu, stt, o);
    smt += __shfl_xor_sync(0xffffffffu, smt, o);
  }
  if (lane == 0) {
    atomicAdd(&g_smt[b], (double)smt);
    atomicAdd(&g_stt[b], (double)stt);
  }

  // combine 4 warps' column sums in shared, then one atomic add per column
  __syncthreads();                        // all warps done with transpose bufs
  float* sflat = (float*)sh2;             // need 4096 floats, have 8448
#pragma unroll
  for (int p = 0; p < 32; ++p) {
    int col = lane + ((BR5(p) ^ 16) << 5);
    sflat[warp * 1024 + col] = csum[p];
  }
  __syncthreads();
  float* cb = g_C + b * NN;
#pragma unroll
  for (int k = 0; k < 8; ++k) {
    int col = threadIdx.x + 128 * k;
    float v = sflat[col] + sflat[1024 + col] + sflat[2048 + col] + sflat[3072 + col];
    atomicAdd(&cb[col], v);               // RED.F32, 8K addresses, low contention
  }
}

// ---- den[b] = dot(C[b], R[b]);  num[b] = dot(ctm, R[b]) -------------------
__global__ void k_red() {
  int b = blockIdx.x;                     // 8 blocks, 1024 threads
  int tid = threadIdx.x;
  float r = g_R[b * NN + tid];
  float sden = g_C[b * NN + tid] * r;
  float snum = g_ctm[tid] * r;
#pragma unroll
  for (int o = 16; o; o >>= 1) {
    sden += __shfl_xor_sync(0xffffffffu, sden, o);
    snum += __shfl_xor_sync(0xffffffffu, snum, o);
  }
  __shared__ float wd[32], wn[32];
  int w = tid >> 5, l = tid & 31;
  if (l == 0) { wd[w] = sden; wn[w] = snum; }
  __syncthreads();
  if (w == 0) {
    float a = wd[l], c = wn[l];
#pragma unroll
    for (int o = 16; o; o >>= 1) {
      a += __shfl_xor_sync(0xffffffffu, a, o);
      c += __shfl_xor_sync(0xffffffffu, c, o);
    }
    if (l == 0) { g_den[b] = (double)a; g_num[b] = (double)c; }
  }
}

// ------- finalize scalar (parallel over batches), then reset accumulators --
__global__ void k_final(float* __restrict__ out) {
  int tid = threadIdx.x;                  // 1024 threads, 1 block
  // threads 0..7 each handle one batch's (div, sqrt) chain in parallel
  double e = 0.0;
  if (tid < NB) {
    float mx = __int_as_float(g_maxbits);
    double norm = 1048576.0 * (double)mx * (double)mx;
    double mu = g_num[tid] / g_den[tid];
    double r = g_smm - 2.0 * mu * g_smt[tid] + mu * mu * g_stt[tid];
    if (r < 0.0) r = 0.0;
    e = sqrt(r / norm);
  }
  if (tid < 32) {
#pragma unroll
    for (int o = 4; o; o >>= 1)
      e += __shfl_down_sync(0xffffffffu, e, o);
    if (tid == 0) out[0] = (float)(e / (double)NB);
  }
  __syncthreads();                        // output computed before reset
#pragma unroll
  for (int i = 0; i < NB; ++i) g_C[tid + i * NN] = 0.0f;
  g_ctm[tid] = 0.0f;
  if (tid < NB) { g_smt[tid] = 0.0; g_stt[tid] = 0.0; }
  if (tid == 0) { g_smm = 0.0; g_maxbits = 0; }
}

extern "C" void kernel_launch(void* const* d_in, const int* in_sizes, int n_in,
                              void* d_out, int out_size) {
  const float* pred  = (const float*)d_in[0];   // [8, 2048]
  // d_in[1] = label, unused by the reference loss
  const float* tmeas = (const float*)d_in[2];   // [1024, 1024]
  (void)in_sizes; (void)n_in; (void)out_size;

  k_prep<<<260, 256>>>(tmeas);
  k_main<<<1024, 128>>>(pred, tmeas);
  k_red<<<NB, 1024>>>();
  k_final<<<1, 1024>>>((float*)d_out);
}